// round 17
// baseline (speedup 1.0000x reference)
#include <cuda_runtime.h>
#include <cuda_bf16.h>
#include <cstdint>

#define BATCH 2
#define SEQ   2048
#define HEADS 16
#define HD    64
#define EMB   1024
#define MROWS (BATCH*SEQ)
#define QKVN  (3*EMB)
#define NKT   (SEQ/64)           // 32 key tiles
#define NCH   (EMB/32)           // 32 k-chunks (16 kp each)

// roped q, fp32 dense [MROWS][EMB]
__device__ float g_q[(size_t)MROWS * EMB];                               // 16.8 MB
// K/V tiles, LDS.128-fragment layout (r16, unchanged)
__device__ uint32_t g_kvsp[(size_t)BATCH * HEADS * NKT * 8192];          // 67.1 MB
// GEMM operands, fragment-block layout: [chunk][pos][32 words]
//   within block: hi(kpl) at (kpl>>3)*16 + (kpl&3)*4 + ((kpl>>2)&1)*2, lo +1
__device__ uint32_t g_xi [(size_t)NCH * MROWS * 32];   // 16.8 MB
__device__ uint32_t g_wqi[(size_t)NCH * QKVN * 32];    // 12.6 MB
__device__ uint32_t g_wpi[(size_t)NCH * EMB * 32];     //  4.2 MB
__device__ uint32_t g_ai [(size_t)NCH * MROWS * 32];   // 16.8 MB

__device__ __forceinline__ uint32_t pack_bf16x2(float e0, float e1) {
    uint32_t r;
    asm("cvt.rn.bf16x2.f32 %0, %1, %2;" : "=r"(r) : "f"(e1), "f"(e0));
    return r;
}
__device__ __forceinline__ void split2(float x, float y, uint32_t& hp, uint32_t& lp) {
    float hx = __bfloat162float(__float2bfloat16_rn(x));
    float hy = __bfloat162float(__float2bfloat16_rn(y));
    hp = pack_bf16x2(hx, hy);
    lp = pack_bf16x2(x - hx, y - hy);
}
__device__ __forceinline__ void mma_bf16(float c[4], const uint32_t a[4], const uint32_t b[2]) {
    asm volatile(
        "mma.sync.aligned.m16n8k16.row.col.f32.bf16.bf16.f32 "
        "{%0,%1,%2,%3}, {%4,%5,%6,%7}, {%8,%9}, {%0,%1,%2,%3};"
        : "+f"(c[0]), "+f"(c[1]), "+f"(c[2]), "+f"(c[3])
        : "r"(a[0]), "r"(a[1]), "r"(a[2]), "r"(a[3]), "r"(b[0]), "r"(b[1]));
}
__device__ __forceinline__ void cp16(uint32_t dst, const void* src) {
    asm volatile("cp.async.cg.shared.global [%0], [%1], 16;" :: "r"(dst), "l"(src));
}
__device__ __forceinline__ void cp_commit() {
    asm volatile("cp.async.commit_group;");
}
// K/V tile word helpers (r16 layout)
__device__ __forceinline__ uint32_t wordK(int key, int dp) {
    return (uint32_t)(key * 64 + ((dp >> 3) << 4) + ((dp & 3) << 2) + (((dp >> 2) & 1) << 1));
}
__device__ __forceinline__ uint32_t wordV(int d, int kp) {
    return (uint32_t)(d * 64 + ((kp >> 3) << 4) + ((kp & 3) << 2) + (((kp >> 2) & 1) << 1));
}

// ---------------------------------------------------------------------------
// prep_a: fp32 A[M][K] -> fragment-block layout g_xi[chunk][m][32]
// block: 32 k (1 chunk) x 64 m; thread tid: m = tid&63, c0 = tid>>6 (0..3)
// writes two uint4 (offsets c0*4 and 16+c0*4) per thread.
// ---------------------------------------------------------------------------
__global__ __launch_bounds__(256) void prep_a(const float* __restrict__ A,
                                              uint32_t* __restrict__ di)
{
    __shared__ float stage[64 * 33];
    const int tid = threadIdx.x;
    const int chunk = blockIdx.x;          // k0 = chunk*32
    const int m0 = blockIdx.y * 64;

    #pragma unroll
    for (int j = 0; j < 2; j++) {
        const int f = tid + j * 256;
        const int r = f >> 3;
        const int c4 = (f & 7) * 4;
        float4 v = *(const float4*)&A[(size_t)(m0 + r) * EMB + chunk * 32 + c4];
        stage[r * 33 + c4 + 0] = v.x;
        stage[r * 33 + c4 + 1] = v.y;
        stage[r * 33 + c4 + 2] = v.z;
        stage[r * 33 + c4 + 3] = v.w;
    }
    __syncthreads();

    const int m_l = tid & 63;
    const int c0  = tid >> 6;              // 0..3
    // kpl = c0, c0+4, c0+8, c0+12 -> frag offsets c0*4, c0*4+2, 16+c0*4, 16+c0*4+2
    uint32_t h0, l0, h1, l1, h2, l2, h3, l3;
    split2(stage[m_l * 33 + 2 * c0],        stage[m_l * 33 + 2 * c0 + 1],        h0, l0);
    split2(stage[m_l * 33 + 2 * (c0 + 4)],  stage[m_l * 33 + 2 * (c0 + 4) + 1],  h1, l1);
    split2(stage[m_l * 33 + 2 * (c0 + 8)],  stage[m_l * 33 + 2 * (c0 + 8) + 1],  h2, l2);
    split2(stage[m_l * 33 + 2 * (c0 + 12)], stage[m_l * 33 + 2 * (c0 + 12) + 1], h3, l3);
    const size_t base = ((size_t)chunk * MROWS + m0 + m_l) * 32;
    *(uint4*)&di[base + c0 * 4]      = make_uint4(h0, l0, h1, l1);
    *(uint4*)&di[base + 16 + c0 * 4] = make_uint4(h2, l2, h3, l3);
}

// ---------------------------------------------------------------------------
// prep_w: fp32 W[K][N] -> fragment-block layout di[chunk][n][32]
// block: chunk (by) x 128 n (bx). Thread owns one n: 32 coalesced row reads,
// 16 splits, 8 contiguous uint4 writes.
// ---------------------------------------------------------------------------
__global__ __launch_bounds__(128) void prep_w(const float* __restrict__ W,
                                              uint32_t* __restrict__ di, int N)
{
    const int n     = blockIdx.x * 128 + threadIdx.x;
    const int chunk = blockIdx.y;
    float wv[32];
    #pragma unroll
    for (int k = 0; k < 32; k++)
        wv[k] = W[(size_t)(chunk * 32 + k) * N + n];
    uint32_t blk[32];
    #pragma unroll
    for (int kpl = 0; kpl < 16; kpl++) {
        const int off = ((kpl >> 3) << 4) + ((kpl & 3) << 2) + (((kpl >> 2) & 1) << 1);
        split2(wv[2 * kpl], wv[2 * kpl + 1], blk[off], blk[off + 1]);
    }
    uint32_t* dst = &di[((size_t)chunk * N + n) * 32];
    #pragma unroll
    for (int seg = 0; seg < 8; seg++)
        *(uint4*)&dst[seg * 4] = make_uint4(blk[4 * seg], blk[4 * seg + 1],
                                            blk[4 * seg + 2], blk[4 * seg + 3]);
}

// ---------------------------------------------------------------------------
// 3xBF16 GEMM, fragment-block operands, LDS.128 fragment loads.
// BM=128 BN=128 BK=32; 256 thr / 8 warps; warp 64x32.
// smem: stage s at s*12288 words; A rows 0..127 pitch 48, B rows at +6144.
// Pitch 48 (=16 mod 32) -> octet bank-conflict-free .128 loads.
// 98304 B total, 2 CTAs/SM. Single barrier per k-iter (r15 scheme).
// ---------------------------------------------------------------------------
#define GSTG_W 12288
__global__ __launch_bounds__(256, 2) void gemm_sp(
    const uint32_t* __restrict__ Ai, const uint32_t* __restrict__ Bi,
    float* __restrict__ C, int Ndim,
    const float* __restrict__ freqs,
    const float* __restrict__ bvec, int mode)
{
    extern __shared__ uint32_t sm[];
    uint32_t smb;
    {
        uint64_t t;
        asm("cvta.to.shared.u64 %0, %1;" : "=l"(t) : "l"(sm));
        smb = (uint32_t)t;
    }

    const int tid  = threadIdx.x;
    const int lane = tid & 31;
    const int warp = tid >> 5;
    const int g    = lane >> 2;
    const int tg   = lane & 3;
    const int warp_m = warp >> 2;
    const int warp_n = warp & 3;
    const int m0 = blockIdx.y * 128;
    const int n0 = blockIdx.x * 128;

    float acc[4][4][4];
    #pragma unroll
    for (int mt = 0; mt < 4; mt++)
        #pragma unroll
        for (int nt = 0; nt < 4; nt++)
            #pragma unroll
            for (int c = 0; c < 4; c++) acc[mt][nt][c] = 0.0f;

    // loader: 2048 16B segs; f = tid + i*256: half=f>>10, pos=(f>>3)&127, seg=f&7
    {
        #pragma unroll
        for (int i = 0; i < 8; i++) {
            const int f = tid + i * 256;
            const int half = f >> 10, pos = (f >> 3) & 127, seg = f & 7;
            const uint32_t* src = (half == 0)
                ? Ai + ((size_t)0 * MROWS + m0 + pos) * 32 + seg * 4
                : Bi + ((size_t)0 * Ndim + n0 + pos) * 32 + seg * 4;
            cp16(smb + (uint32_t)(half * 6144 + pos * 48 + seg * 4) * 4u, src);
        }
        cp_commit();
    }

    for (int it = 0; it < NCH; it++) {
        const int cur = it & 1;
        asm volatile("cp.async.wait_group 0;");
        __syncthreads();
        if (it + 1 < NCH) {
            const uint32_t sb = smb + (uint32_t)((cur ^ 1) * GSTG_W) * 4u;
            #pragma unroll
            for (int i = 0; i < 8; i++) {
                const int f = tid + i * 256;
                const int half = f >> 10, pos = (f >> 3) & 127, seg = f & 7;
                const uint32_t* src = (half == 0)
                    ? Ai + ((size_t)(it + 1) * MROWS + m0 + pos) * 32 + seg * 4
                    : Bi + ((size_t)(it + 1) * Ndim + n0 + pos) * 32 + seg * 4;
                cp16(sb + (uint32_t)(half * 6144 + pos * 48 + seg * 4) * 4u, src);
            }
            cp_commit();
        }

        const uint32_t* As = sm + cur * GSTG_W;
        const uint32_t* Bs = As + 6144;

        #pragma unroll
        for (int kc = 0; kc < 2; kc++) {
            uint32_t bh[4][2], bl[4][2];
            #pragma unroll
            for (int nt = 0; nt < 4; nt++) {
                const int nc = warp_n * 32 + nt * 8 + g;
                uint4 f = *(const uint4*)&Bs[nc * 48 + kc * 16 + tg * 4];
                bh[nt][0] = f.x; bl[nt][0] = f.y;
                bh[nt][1] = f.z; bl[nt][1] = f.w;
            }
            #pragma unroll
            for (int mt = 0; mt < 4; mt++) {
                const int mr = warp_m * 64 + mt * 16;
                uint4 r0 = *(const uint4*)&As[(mr + g) * 48 + kc * 16 + tg * 4];
                uint4 r1 = *(const uint4*)&As[(mr + g + 8) * 48 + kc * 16 + tg * 4];
                uint32_t ah[4]  = {r0.x, r1.x, r0.z, r1.z};
                uint32_t al_[4] = {r0.y, r1.y, r0.w, r1.w};
                #pragma unroll
                for (int nt = 0; nt < 4; nt++) {
                    mma_bf16(acc[mt][nt], al_, bh[nt]);
                    mma_bf16(acc[mt][nt], ah,  bl[nt]);
                    mma_bf16(acc[mt][nt], ah,  bh[nt]);
                }
            }
        }
    }

    // epilogue (mode 1: RoPE + q store + K/V scatter (r16 layout); mode 0: +bias)
    #pragma unroll
    for (int mt = 0; mt < 4; mt++) {
        const int m = m0 + warp_m * 64 + mt * 16 + g;
        #pragma unroll
        for (int nt = 0; nt < 4; nt++) {
            const int n = n0 + warp_n * 32 + nt * 8 + 2 * tg;
            float a0 = acc[mt][nt][0], a1 = acc[mt][nt][1];
            float a2 = acc[mt][nt][2], a3 = acc[mt][nt][3];
            if (mode == 0) {
                const float b0 = bvec[n], b1 = bvec[n + 1];
                *(float2*)&C[(size_t)m * Ndim + n]       = make_float2(a0 + b0, a1 + b1);
                *(float2*)&C[(size_t)(m + 8) * Ndim + n] = make_float2(a2 + b0, a3 + b1);
            } else {
                const int seq = m & (SEQ - 1);
                const int bb  = m >> 11;
                if (n < 2 * EMB) {
                    const int d0 = n & (HD - 1);
                    const float* f0p = &freqs[(size_t)seq * HD + d0];
                    const float* f1p = f0p + (size_t)8 * HD;
                    float f0 = f0p[0], f1 = f0p[1];
                    float e0 = a0 * f0 - a1 * f1;
                    float e1 = a1 * f0 + a0 * f1;
                    float h0 = f1p[0], h1 = f1p[1];
                    float e2 = a2 * h0 - a3 * h1;
                    float e3 = a3 * h0 + a2 * h1;
                    if (n < EMB) {
                        *(float2*)&C[(size_t)m * EMB + n]       = make_float2(e0, e1);
                        *(float2*)&C[(size_t)(m + 8) * EMB + n] = make_float2(e2, e3);
                    } else {
                        const int hh = (n - EMB) >> 6;
                        const int d  = n & 63;
                        const int dp = d >> 1;
                        const int kt = seq >> 6, key = seq & 63;
                        uint32_t* dst = g_kvsp + ((size_t)(bb * HEADS + hh) * NKT + kt) * 8192;
                        uint32_t hp, lp;
                        split2(e0, e1, hp, lp);
                        *(uint2*)&dst[wordK(key, dp)]     = make_uint2(hp, lp);
                        split2(e2, e3, hp, lp);
                        *(uint2*)&dst[wordK(key + 8, dp)] = make_uint2(hp, lp);
                    }
                } else {
                    const int hh = (n - 2 * EMB) >> 6;
                    const int d  = n & 63;
                    const int kt = seq >> 6, key = seq & 63;
                    uint32_t* dst = g_kvsp + ((size_t)(bb * HEADS + hh) * NKT + kt) * 8192 + 4096;
                    float p0 = __shfl_xor_sync(0xffffffffu, a0, 4);
                    float p1 = __shfl_xor_sync(0xffffffffu, a1, 4);
                    float p2 = __shfl_xor_sync(0xffffffffu, a2, 4);
                    float p3 = __shfl_xor_sync(0xffffffffu, a3, 4);
                    const int u0 = key >> 1;
                    uint32_t hp, lp;
                    if ((g & 1) == 0) {
                        split2(a0, p0, hp, lp);
                        *(uint2*)&dst[wordV(d, u0)]     = make_uint2(hp, lp);
                        split2(a2, p2, hp, lp);
                        *(uint2*)&dst[wordV(d, u0 + 4)] = make_uint2(hp, lp);
                    } else {
                        split2(p1, a1, hp, lp);
                        *(uint2*)&dst[wordV(d + 1, u0)]     = make_uint2(hp, lp);
                        split2(p3, a3, hp, lp);
                        *(uint2*)&dst[wordV(d + 1, u0 + 4)] = make_uint2(hp, lp);
                    }
                }
            }
        }
    }
}

// ---------------------------------------------------------------------------
// Flash attention (r16 core, 422us, unchanged) — epilogue writes fragment-
// block proj-A operand g_ai.
// ---------------------------------------------------------------------------
#define STG_W 10240

__device__ __forceinline__ void copy_kv(const uint32_t* __restrict__ gsrc,
                                        uint32_t sbase_b, int tid)
{
    #pragma unroll
    for (int i = 0; i < 8; i++) {
        const int q = tid + i * 256;
        const int half = q >> 10;
        const int r = (q >> 4) & 63;
        const int c = (q & 15) * 4;
        cp16(sbase_b + (uint32_t)(half * 5120 + r * 80 + c) * 4u,
             gsrc + half * 4096 + r * 64 + c);
    }
}

__global__ __launch_bounds__(256, 2) void attn_kernel(const float* __restrict__ bias)
{
    extern __shared__ uint32_t sm[];
    uint32_t smb;
    {
        uint64_t t;
        asm("cvta.to.shared.u64 %0, %1;" : "=l"(t) : "l"(sm));
        smb = (uint32_t)t;
    }

    const int tid  = threadIdx.x;
    const int lane = tid & 31;
    const int w    = tid >> 5;
    const int g    = lane >> 2;
    const int tg   = lane & 3;
    const int q0   = blockIdx.x * 128;
    const int h    = blockIdx.y;
    const int b    = blockIdx.z;

    const int rowA = q0 + w * 16 + g;
    const float scale = 0.125f;
    const uint32_t* gtiles = g_kvsp + (size_t)(b * HEADS + h) * NKT * 8192;

    uint32_t qh[4][4], ql[4][4];
    {
        const float* qA = &g_q[(size_t)(b * SEQ + rowA) * EMB + h * HD];
        const float* qB = qA + (size_t)8 * EMB;
        #pragma unroll
        for (int ks = 0; ks < 4; ks++) {
            const int d0 = ks * 16 + 2 * tg;
            float2 x0 = *(const float2*)&qA[d0];
            float2 x1 = *(const float2*)&qB[d0];
            float2 x2 = *(const float2*)&qA[d0 + 8];
            float2 x3 = *(const float2*)&qB[d0 + 8];
            split2(x0.x * scale, x0.y * scale, qh[ks][0], ql[ks][0]);
            split2(x1.x * scale, x1.y * scale, qh[ks][1], ql[ks][1]);
            split2(x2.x * scale, x2.y * scale, qh[ks][2], ql[ks][2]);
            split2(x3.x * scale, x3.y * scale, qh[ks][3], ql[ks][3]);
        }
    }

    float o[8][4];
    #pragma unroll
    for (int nb = 0; nb < 8; nb++)
        #pragma unroll
        for (int j = 0; j < 4; j++) o[nb][j] = 0.0f;
    float m0 = -1e30f, m1 = -1e30f, l0 = 0.0f, l1 = 0.0f;

    copy_kv(gtiles, smb, tid);
    cp_commit();

    for (int kt = 0; kt < NKT; kt++) {
        const int cur = kt & 1;
        asm volatile("cp.async.wait_group 0;");
        __syncthreads();
        if (kt + 1 < NKT) {
            copy_kv(gtiles + (size_t)(kt + 1) * 8192,
                    smb + (cur ^ 1) * (STG_W * 4), tid);
            cp_commit();
        }

        const uint32_t* Ks = sm + cur * STG_W;
        const uint32_t* Vs = Ks + 5120;

        float s[8][4];
        #pragma unroll
        for (int nb = 0; nb < 8; nb++)
            #pragma unroll
            for (int j = 0; j < 4; j++) s[nb][j] = 0.0f;

        #pragma unroll
        for (int ks = 0; ks < 4; ks++) {
            #pragma unroll
            for (int nb = 0; nb < 8; nb++) {
                uint4 f = *(const uint4*)&Ks[(8 * nb + g) * 80 + ks * 16 + tg * 4];
                uint32_t bh[2] = {f.x, f.z};
                uint32_t bl[2] = {f.y, f.w};
                mma_bf16(s[nb], ql[ks], bh);
                mma_bf16(s[nb], qh[ks], bl);
                mma_bf16(s[nb], qh[ks], bh);
            }
        }

        const float* bp = &bias[((size_t)h * SEQ + rowA) * SEQ + kt * 64];
        float mx0 = -1e30f, mx1 = -1e30f;
        #pragma unroll
        for (int nb = 0; nb < 8; nb++) {
            float2 b0 = __ldcs((const float2*)(bp + nb * 8 + 2 * tg));
            float2 b1 = __ldcs((const float2*)(bp + (size_t)8 * SEQ + nb * 8 + 2 * tg));
            s[nb][0] += b0.x; s[nb][1] += b0.y;
            s[nb][2] += b1.x; s[nb][3] += b1.y;
            mx0 = fmaxf(mx0, fmaxf(s[nb][0], s[nb][1]));
            mx1 = fmaxf(mx1, fmaxf(s[nb][2], s[nb][3]));
        }
        mx0 = fmaxf(mx0, __shfl_xor_sync(0xffffffffu, mx0, 1));
        mx0 = fmaxf(mx0, __shfl_xor_sync(0xffffffffu, mx0, 2));
        mx1 = fmaxf(mx1, __shfl_xor_sync(0xffffffffu, mx1, 1));
        mx1 = fmaxf(mx1, __shfl_xor_sync(0xffffffffu, mx1, 2));
        const float nm0 = fmaxf(m0, mx0), nm1 = fmaxf(m1, mx1);
        const float al0 = __expf(m0 - nm0), al1 = __expf(m1 - nm1);
        m0 = nm0; m1 = nm1;

        float ts0 = 0.0f, ts1 = 0.0f;
        #pragma unroll
        for (int nb = 0; nb < 8; nb++) {
            s[nb][0] = __expf(s[nb][0] - nm0);
            s[nb][1] = __expf(s[nb][1] - nm0);
            s[nb][2] = __expf(s[nb][2] - nm1);
            s[nb][3] = __expf(s[nb][3] - nm1);
            ts0 += s[nb][0] + s[nb][1];
            ts1 += s[nb][2] + s[nb][3];
        }
        ts0 += __shfl_xor_sync(0xffffffffu, ts0, 1);
        ts0 += __shfl_xor_sync(0xffffffffu, ts0, 2);
        ts1 += __shfl_xor_sync(0xffffffffu, ts1, 1);
        ts1 += __shfl_xor_sync(0xffffffffu, ts1, 2);
        l0 = l0 * al0 + ts0;
        l1 = l1 * al1 + ts1;
        #pragma unroll
        for (int nb = 0; nb < 8; nb++) {
            o[nb][0] *= al0; o[nb][1] *= al0;
            o[nb][2] *= al1; o[nb][3] *= al1;
        }

        #pragma unroll
        for (int j = 0; j < 4; j++) {
            uint32_t ah[4], al_[4];
            split2(s[2 * j][0],     s[2 * j][1],     ah[0], al_[0]);
            split2(s[2 * j][2],     s[2 * j][3],     ah[1], al_[1]);
            split2(s[2 * j + 1][0], s[2 * j + 1][1], ah[2], al_[2]);
            split2(s[2 * j + 1][2], s[2 * j + 1][3], ah[3], al_[3]);
            #pragma unroll
            for (int nb = 0; nb < 8; nb++) {
                uint4 f = *(const uint4*)&Vs[(8 * nb + g) * 80 + j * 16 + tg * 4];
                uint32_t vh[2] = {f.x, f.z};
                uint32_t vl[2] = {f.y, f.w};
                mma_bf16(o[nb], al_, vh);
                mma_bf16(o[nb], ah,  vl);
                mma_bf16(o[nb], ah,  vh);
            }
        }
    }

    // epilogue: normalize + write fragment-block proj-A operand
    // kp = h*32 + nb*4 + tg -> chunk = h*2 + (nb>>2),
    // off = ((nb&3)>>1)*16 + tg*4 + (nb&1)*2, uint2 {hi, lo}
    const float inv0 = 1.0f / l0, inv1 = 1.0f / l1;
    const int mA = b * SEQ + rowA;
    #pragma unroll
    for (int nb = 0; nb < 8; nb++) {
        const int chunk = h * 2 + (nb >> 2);
        const int off = (((nb & 3) >> 1) << 4) + (tg << 2) + ((nb & 1) << 1);
        uint32_t hh, ll;
        split2(o[nb][0] * inv0, o[nb][1] * inv0, hh, ll);
        *(uint2*)&g_ai[((size_t)chunk * MROWS + mA) * 32 + off]     = make_uint2(hh, ll);
        split2(o[nb][2] * inv1, o[nb][3] * inv1, hh, ll);
        *(uint2*)&g_ai[((size_t)chunk * MROWS + mA + 8) * 32 + off] = make_uint2(hh, ll);
    }
}

// ---------------------------------------------------------------------------
extern "C" void kernel_launch(void* const* d_in, const int* in_sizes, int n_in,
                              void* d_out, int out_size)
{
    const float* x      = (const float*)d_in[0];
    const float* freqs  = (const float*)d_in[1];
    const float* bias   = (const float*)d_in[2];
    const float* w_qkv  = (const float*)d_in[3];
    const float* w_proj = (const float*)d_in[4];
    const float* b_proj = (const float*)d_in[5];
    float* out = (float*)d_out;

    float* q_ptr; cudaGetSymbolAddress((void**)&q_ptr, g_q);
    uint32_t *xi, *wqi, *wpi, *ai;
    cudaGetSymbolAddress((void**)&xi,  g_xi);
    cudaGetSymbolAddress((void**)&wqi, g_wqi);
    cudaGetSymbolAddress((void**)&wpi, g_wpi);
    cudaGetSymbolAddress((void**)&ai,  g_ai);

    const int gemm_smem = 2 * GSTG_W * 4;   // 98304 B
    const int attn_smem = 2 * STG_W * 4;    // 81920 B
    cudaFuncSetAttribute(gemm_sp, cudaFuncAttributeMaxDynamicSharedMemorySize, gemm_smem);
    cudaFuncSetAttribute(attn_kernel, cudaFuncAttributeMaxDynamicSharedMemorySize, attn_smem);

    // attn stays our 4th launch -> ncu capture slot
    prep_a<<<dim3(NCH, MROWS / 64), 256>>>(x, xi);                                   // 1
    prep_w<<<dim3(QKVN / 128, NCH), 128>>>(w_qkv, wqi, QKVN);                        // 2
    gemm_sp<<<dim3(QKVN / 128, MROWS / 128), 256, gemm_smem>>>(                      // 3
        xi, wqi, q_ptr, QKVN, freqs, nullptr, 1);
    attn_kernel<<<dim3(SEQ / 128, HEADS, BATCH), 256, attn_smem>>>(bias);            // 4 <- profiled
    prep_w<<<dim3(EMB / 128, NCH), 128>>>(w_proj, wpi, EMB);                         // 5
    gemm_sp<<<dim3(EMB / 128, MROWS / 128), 256, gemm_smem>>>(                       // 6
        ai, wpi, out, EMB, nullptr, b_proj, 0);
}